// round 3
// baseline (speedup 1.0000x reference)
#include <cuda_runtime.h>

// Problem constants (fixed by reference setup_inputs):
//   x:    [8, 256, 256, 64] f32
//   flow: [8, 252, 252, 25] f32
//   out:  [8, 252, 252, 64] f32, ksize = 5
#define KS 5
#define B_ 8
#define H_ 256
#define W_ 256
#define C_ 64
#define HO 252
#define WO 252

// Block: 16 channel-groups (x) * 16 j-groups (y) = 256 threads.
// Each thread: 4 consecutive j pixels * 4 consecutive channels (float4).
// Per di: 8 float4 x-loads serve all 4 pixels * 5 dj taps (register reuse).
__global__ __launch_bounds__(256) void dfl_kernel(
    const float* __restrict__ x,
    const float* __restrict__ flow,
    float* __restrict__ out)
{
    __shared__ float s_flow[64 * 25];  // flow for the 64 output pixels this block covers

    const int tx = threadIdx.x;        // channel group 0..15  -> c = 4*tx
    const int ty = threadIdx.y;        // j group 0..15        -> j0 = j_base + 4*ty
    const int i  = blockIdx.y;         // output row 0..251
    const int b  = blockIdx.z;         // batch 0..7
    const int j_base = blockIdx.x * 64;

    // Cooperative, coalesced flow stage: 64 pixels * 25 taps (contiguous in gmem).
    {
        const int tid  = ty * 16 + tx;
        const int npix = min(64, WO - j_base);
        const int nflt = npix * 25;
        const float* fsrc = flow + ((size_t)(b * HO + i) * WO + j_base) * 25;
        for (int idx = tid; idx < nflt; idx += 256)
            s_flow[idx] = fsrc[idx];
    }
    __syncthreads();

    const int j0 = j_base + ty * 4;
    if (j0 >= WO) return;              // only last block's last j-group (1/64 waste)

    const int c = tx * 4;

    float4 acc[4];
    #pragma unroll
    for (int jj = 0; jj < 4; ++jj) acc[jj] = make_float4(0.f, 0.f, 0.f, 0.f);

    #pragma unroll
    for (int di = 0; di < KS; ++di) {
        // 8 float4 loads at row i+di cover j0 .. j0+7 (max 255 = W-1, never OOB)
        const float4* __restrict__ xp = reinterpret_cast<const float4*>(
            x + (((size_t)(b * H_ + i + di) * W_ + j0) * C_ + c));
        float4 xv[8];
        #pragma unroll
        for (int u = 0; u < 8; ++u)
            xv[u] = xp[u * (C_ / 4)];

        #pragma unroll
        for (int jj = 0; jj < 4; ++jj) {
            #pragma unroll
            for (int dj = 0; dj < KS; ++dj) {
                // broadcast LDS: all 16 tx threads read the same address
                const float f = s_flow[(ty * 4 + jj) * 25 + di * KS + dj];
                const float4 v = xv[jj + dj];
                acc[jj].x = fmaf(v.x, f, acc[jj].x);
                acc[jj].y = fmaf(v.y, f, acc[jj].y);
                acc[jj].z = fmaf(v.z, f, acc[jj].z);
                acc[jj].w = fmaf(v.w, f, acc[jj].w);
            }
        }
    }

    float4* __restrict__ op = reinterpret_cast<float4*>(
        out + (((size_t)(b * HO + i) * WO + j0) * C_ + c));
    #pragma unroll
    for (int jj = 0; jj < 4; ++jj)
        op[jj * (C_ / 4)] = acc[jj];
}

extern "C" void kernel_launch(void* const* d_in, const int* in_sizes, int n_in,
                              void* d_out, int out_size) {
    const float* x    = (const float*)d_in[0];
    const float* flow = (const float*)d_in[1];
    // d_in[2] is ksize (compile-time 5 here), ignored.
    float* out = (float*)d_out;

    dim3 grid(4 /* ceil(63 j-groups / 16) */, HO, B_);
    dim3 block(16, 16);
    dfl_kernel<<<grid, block>>>(x, flow, out);
}

// round 7
// speedup vs baseline: 1.1061x; 1.1061x over previous
#include <cuda_runtime.h>

// Problem constants (fixed by reference setup_inputs):
//   x:    [8, 256, 256, 64] f32
//   flow: [8, 252, 252, 25] f32
//   out:  [8, 252, 252, 64] f32, ksize = 5
#define KS 5
#define B_ 8
#define H_ 256
#define W_ 256
#define C_ 64
#define HO 252
#define WO 252

// Packed dual-FMA: acc(f32x2) += x(f32x2) * f(f32x2). Only reachable via PTX.
#define FMA2(acc, xv, ff) \
    asm("fma.rn.f32x2 %0, %1, %2, %0;" : "+l"(acc) : "l"(xv), "l"(ff))

// Block: 16 channel-groups (tx) * 16 j-groups (ty) = 256 threads.
// Each thread: 2 output rows (i, i+1) * 4 j pixels * 4 channels.
// Loop over the 6 shared x rows; each row's 8 float4 loads feed both outputs.
__global__ __launch_bounds__(256, 3) void dfl_kernel(
    const float* __restrict__ x,
    const float* __restrict__ flow,
    float* __restrict__ out)
{
    // flow for 2 output rows * 64 pixels * 25 taps, pre-duplicated as (f,f)
    // pairs so LDS.64 yields a packed f32x2 multiplier directly.
    __shared__ float2 s_flow[2 * 64 * 25];

    const int tx = threadIdx.x;          // channel group: c = 4*tx
    const int ty = threadIdx.y;          // j group: j0 = j_base + 4*ty
    const int i  = blockIdx.y * 2;       // output rows i, i+1 (i <= 250)
    const int b  = blockIdx.z;
    const int j_base = blockIdx.x * 64;

    // Cooperative flow stage (coalesced reads, duplicated writes).
    {
        const int tid  = ty * 16 + tx;
        const int npix = min(64, WO - j_base);
        const int n    = npix * 25;
        const float* f0 = flow + ((size_t)(b * HO + i) * WO + j_base) * 25;
        const float* f1 = f0 + (size_t)WO * 25;
        for (int idx = tid; idx < n; idx += 256) {
            const float v0 = f0[idx];
            const float v1 = f1[idx];
            s_flow[idx]           = make_float2(v0, v0);
            s_flow[64 * 25 + idx] = make_float2(v1, v1);
        }
    }
    __syncthreads();

    const int j0 = j_base + ty * 4;
    if (j0 >= WO) return;                // only last block's ty=15 group

    const int c = tx * 4;

    ulonglong2 acc[2][4];                // [row][jj], each = 4 packed f32
    #pragma unroll
    for (int o = 0; o < 2; ++o)
        #pragma unroll
        for (int jj = 0; jj < 4; ++jj) { acc[o][jj].x = 0ull; acc[o][jj].y = 0ull; }

    const float2* fl0 = s_flow + (ty * 4) * 25;            // row i
    const float2* fl1 = s_flow + 64 * 25 + (ty * 4) * 25;  // row i+1

    #pragma unroll
    for (int r = 0; r < 6; ++r) {        // x rows i+r; max i+5 = 255, in-bounds
        const ulonglong2* __restrict__ xp = reinterpret_cast<const ulonglong2*>(
            x + (((size_t)(b * H_ + i + r) * W_ + j0) * C_ + c));
        ulonglong2 xv[8];                // covers j0..j0+7 (max 255, in-bounds)
        #pragma unroll
        for (int u = 0; u < 8; ++u)
            xv[u] = xp[u * (C_ / 4)];

        if (r <= 4) {                    // contributes to out-row i with di = r
            #pragma unroll
            for (int jj = 0; jj < 4; ++jj) {
                #pragma unroll
                for (int dj = 0; dj < KS; ++dj) {
                    const unsigned long long f =
                        *reinterpret_cast<const unsigned long long*>(
                            &fl0[jj * 25 + r * KS + dj]);
                    FMA2(acc[0][jj].x, xv[jj + dj].x, f);
                    FMA2(acc[0][jj].y, xv[jj + dj].y, f);
                }
            }
        }
        if (r >= 1) {                    // contributes to out-row i+1 with di = r-1
            #pragma unroll
            for (int jj = 0; jj < 4; ++jj) {
                #pragma unroll
                for (int dj = 0; dj < KS; ++dj) {
                    const unsigned long long f =
                        *reinterpret_cast<const unsigned long long*>(
                            &fl1[jj * 25 + (r - 1) * KS + dj]);
                    FMA2(acc[1][jj].x, xv[jj + dj].x, f);
                    FMA2(acc[1][jj].y, xv[jj + dj].y, f);
                }
            }
        }
    }

    #pragma unroll
    for (int o = 0; o < 2; ++o) {
        ulonglong2* __restrict__ op = reinterpret_cast<ulonglong2*>(
            out + (((size_t)(b * HO + i + o) * WO + j0) * C_ + c));
        #pragma unroll
        for (int jj = 0; jj < 4; ++jj)
            op[jj * (C_ / 4)] = acc[o][jj];
    }
}

extern "C" void kernel_launch(void* const* d_in, const int* in_sizes, int n_in,
                              void* d_out, int out_size) {
    const float* x    = (const float*)d_in[0];
    const float* flow = (const float*)d_in[1];
    float* out = (float*)d_out;

    dim3 grid(4 /* ceil(63 j-groups / 16) */, HO / 2, B_);
    dim3 block(16, 16);
    dfl_kernel<<<grid, block>>>(x, flow, out);
}